// round 5
// baseline (speedup 1.0000x reference)
#include <cuda_runtime.h>
#include <math.h>

// Batched EKF, decomposed into three independent 2x2 filters per segment.
// Key insight this round: block C ({theta,omega}) is LINEAR and data-independent
// => its gain/innovation-variance/logdet sequence is identical for all segments.
// One lane per block computes it once into smem; C per-segment work collapses
// to ~8 FFMA/step. Warps 0-1: A+B filters (1 segment/thread, ILP-2).
// Warp 2: C filters (2 segments/thread, gains from smem).

#define SEGS_PER_BLOCK 64
#define THREADS 96

__device__ float g_partials[1024];
__device__ int   g_count = 0;

__device__ __forceinline__ float tanh_fast(float x){ float y; asm("tanh.approx.f32 %0, %1;" : "=f"(y) : "f"(x)); return y; }
__device__ __forceinline__ float rcp_fast (float x){ float y; asm("rcp.approx.f32 %0, %1;"  : "=f"(y) : "f"(x)); return y; }
__device__ __forceinline__ float lg2_fast (float x){ float y; asm("lg2.approx.f32 %0, %1;"  : "=f"(y) : "f"(x)); return y; }

__global__ void __launch_bounds__(THREADS) ekf_kernel(
    const float* __restrict__ params,
    const float* __restrict__ cp,
    const float* __restrict__ init_state,
    const float* __restrict__ meas,
    float* __restrict__ out,
    int N, int T)
{
    const float DT    = 1.0f / 120.0f;
    const float GRAV  = 9.81f;
    const float KS    = 100.0f;
    const float WRAP  = 4.71238898038469f;   // 1.5*pi
    const float TWOPI = 6.283185307179586f;
    const float LN2   = 0.6931471805599453f;

    extern __shared__ float4 sg[];           // sg[0..T-1] = {k0C, k1C, iSC, 0}
    float* slog = (float*)&sg[T];            // lg2-sum of S_C over t

    const float fric = fabsf(params[0]);
    const float damp = fabsf(params[1]);
    const float fg    = fric * GRAV;
    const float cF    = 1.0f - DT * damp;
    const float DTfgk = DT * fg * KS;

    int tid  = threadIdx.x;
    int w    = tid >> 5;
    int lane = tid & 31;
    int base = blockIdx.x * SEGS_PER_BLOCK;

    float loss = 0.0f;

    if (w == 2) {
        // ================= C warp =================
        const float R2v = expf(cp[2]);
        const float Qt  = expf(cp[5]);
        const float Qo  = expf(cp[6]);
        const float cF2 = cF * cF;

        if (lane == 0) {
            // serial Riccati recursion, segment-independent
            float p00 = 0.01f, p01 = 0.0f, p11 = 0.01f, sl = 0.0f;
            for (int t = 0; t < T; t++) {
                float Pp00 = fmaf(DT, fmaf(DT, p11, p01 + p01), p00) + Qt;
                float Pp01 = cF * fmaf(DT, p11, p01);
                float Pp11 = fmaf(cF2, p11, Qo);
                float S  = Pp00 + R2v;
                float iS = rcp_fast(S);
                float k0 = Pp00 * iS, k1 = Pp01 * iS;
                sg[t] = make_float4(k0, k1, iS, 0.0f);
                float om = 1.0f - k0;
                p00 = Pp00 * om; p01 = Pp01 * om;
                p11 = fmaf(-k1, Pp01, Pp11);
                sl += lg2_fast(S);
            }
            *slog = sl;
        }
        __syncwarp();

        int n0 = base + lane, n1 = base + 32 + lane;
        bool v0 = n0 < N, v1 = n1 < N;
        float x0=0.f, u0=0.f, x1=0.f, u1=0.f;
        if (v0) { x0 = init_state[n0*6+4]; u0 = init_state[n0*6+5]; }
        if (v1) { x1 = init_state[n1*6+4]; u1 = init_state[n1*6+5]; }
        const float* m0 = meas + (size_t)n0 * T * 3;
        const float* m1 = meas + (size_t)n1 * T * 3;
        float am0 = 0.f, am1 = 0.f;

        if ((T & 3) == 0) {
            int G = T >> 2;
            // prefetch group 0
            float za[4], zb[4];
            #pragma unroll
            for (int i = 0; i < 4; i++) {
                za[i] = v0 ? m0[i*3+2] : 0.f;
                zb[i] = v1 ? m1[i*3+2] : 0.f;
            }
            for (int g = 0; g < G; g++) {
                float na[4], nb[4];
                if (g + 1 < G) {
                    int o = (g + 1) * 12 + 2;
                    #pragma unroll
                    for (int i = 0; i < 4; i++) {
                        na[i] = v0 ? m0[o + i*3] : 0.f;
                        nb[i] = v1 ? m1[o + i*3] : 0.f;
                    }
                }
                #pragma unroll
                for (int i = 0; i < 4; i++) {
                    float4 gn = sg[g*4 + i];
                    // seg0
                    float xp = fmaf(DT, u0, x0);
                    float vp = cF * u0;
                    float y  = za[i] - xp;
                    if      (y >  WRAP) y -= TWOPI;
                    else if (y < -WRAP) y += TWOPI;
                    x0 = fmaf(gn.x, y, xp);  u0 = fmaf(gn.y, y, vp);
                    am0 = fmaf(y * y, gn.z, am0);
                    // seg1
                    xp = fmaf(DT, u1, x1);
                    vp = cF * u1;
                    y  = zb[i] - xp;
                    if      (y >  WRAP) y -= TWOPI;
                    else if (y < -WRAP) y += TWOPI;
                    x1 = fmaf(gn.x, y, xp);  u1 = fmaf(gn.y, y, vp);
                    am1 = fmaf(y * y, gn.z, am1);
                }
                #pragma unroll
                for (int i = 0; i < 4; i++) { za[i] = na[i]; zb[i] = nb[i]; }
            }
        } else {
            for (int t = 0; t < T; t++) {
                float4 gn = sg[t];
                float z0 = v0 ? m0[t*3+2] : 0.f;
                float z1 = v1 ? m1[t*3+2] : 0.f;
                float xp = fmaf(DT, u0, x0), vp = cF * u0;
                float y = z0 - xp;
                if (y > WRAP) y -= TWOPI; else if (y < -WRAP) y += TWOPI;
                x0 = fmaf(gn.x, y, xp); u0 = fmaf(gn.y, y, vp);
                am0 = fmaf(y*y, gn.z, am0);
                xp = fmaf(DT, u1, x1); vp = cF * u1;
                y = z1 - xp;
                if (y > WRAP) y -= TWOPI; else if (y < -WRAP) y += TWOPI;
                x1 = fmaf(gn.x, y, xp); u1 = fmaf(gn.y, y, vp);
                am1 = fmaf(y*y, gn.z, am1);
            }
        }
        loss = 0.5f * ((v0 ? am0 : 0.f) + (v1 ? am1 : 0.f));
        if (lane == 0) {
            int nv = N - base;
            if (nv > SEGS_PER_BLOCK) nv = SEGS_PER_BLOCK;
            if (nv < 0) nv = 0;
            loss += 0.5f * LN2 * (*slog) * (float)nv;   // C logdet, all segs of block
        }
    } else {
        // ================= A+B warps =================
        const float R0 = expf(cp[0]);
        const float R1 = expf(cp[1]);
        const float Qp = expf(cp[3]);
        const float Qv = expf(cp[4]);

        int n = base + w * 32 + lane;
        if (n < N) {
            float xA = init_state[n*6+0], vA = init_state[n*6+2];
            float xB = init_state[n*6+1], vB = init_state[n*6+3];
            float pA00=0.01f, pA01=0.f, pA11=0.01f;
            float pB00=0.01f, pB01=0.f, pB11=0.01f;

            const float*  mp  = meas + (size_t)n * T * 3;
            const float4* mp4 = (const float4*)mp;

            float acc_l2 = 0.f, acc_m = 0.f;

#define SUB(x_, v_, p00_, p01_, p11_, Rc_, z_, sp_) do {                       \
            float th  = tanh_fast(KS * v_);                                    \
            float xp  = fmaf(DT, v_, x_);                                      \
            float vp  = fmaf(-DT, fmaf(fg, th, damp * v_), v_);                \
            float a   = fmaf(-DTfgk, fmaf(-th, th, 1.0f), cF);                 \
            float Pp00 = fmaf(DT, fmaf(DT, p11_, p01_ + p01_), p00_) + Qp;     \
            float Pp01 = a * fmaf(DT, p11_, p01_);                             \
            float Pp11 = fmaf(a * a, p11_, Qv);                                \
            float y  = (z_) - xp;                                              \
            float S  = Pp00 + Rc_;                                             \
            float iS = rcp_fast(S);                                            \
            float k0 = Pp00 * iS, k1 = Pp01 * iS;                              \
            x_ = fmaf(k0, y, xp);  v_ = fmaf(k1, y, vp);                       \
            float om = 1.0f - k0;                                              \
            p00_ = Pp00 * om; p01_ = Pp01 * om;                                \
            p11_ = fmaf(-k1, Pp01, Pp11);                                      \
            acc_m = fmaf(y * y, iS, acc_m);                                    \
            sp_ *= S;                                                          \
        } while (0)

#define STEP2(z0_, z1_) do {                                                   \
            SUB(xA, vA, pA00, pA01, pA11, R0, (z0_), spA);                     \
            SUB(xB, vB, pB00, pB01, pB11, R1, (z1_), spB);                     \
        } while (0)

            if ((T & 3) == 0) {
                int G = T >> 2;
                float4 c0 = mp4[0], c1 = mp4[1], c2 = mp4[2];
                for (int g = 0; g < G; g++) {
                    float4 d0, d1, d2;
                    if (g + 1 < G) {
                        int b = (g + 1) * 3;
                        d0 = mp4[b]; d1 = mp4[b+1]; d2 = mp4[b+2];
                    }
                    float spA = 1.f, spB = 1.f;
                    STEP2(c0.x, c0.y);
                    STEP2(c0.w, c1.x);
                    STEP2(c1.z, c1.w);
                    STEP2(c2.y, c2.z);
                    acc_l2 += lg2_fast(spA * spB);
                    c0 = d0; c1 = d1; c2 = d2;
                }
            } else {
                for (int t = 0; t < T; t++) {
                    float spA = 1.f, spB = 1.f;
                    STEP2(mp[t*3+0], mp[t*3+1]);
                    acc_l2 += lg2_fast(spA * spB);
                }
            }
#undef STEP2
#undef SUB
            loss = 0.5f * fmaf(LN2, acc_l2, acc_m);
        }
    }

    // ---- deterministic block reduction ----
    __shared__ float red[3];
    #pragma unroll
    for (int o = 16; o > 0; o >>= 1)
        loss += __shfl_down_sync(0xffffffffu, loss, o);
    if (lane == 0) red[w] = loss;
    __syncthreads();

    __shared__ int s_last;
    if (tid == 0) {
        g_partials[blockIdx.x] = red[0] + red[1] + red[2];
        __threadfence();
        int old = atomicAdd(&g_count, 1);
        s_last = (old == (int)gridDim.x - 1);
    }
    __syncthreads();
    if (s_last && w == 0) {
        __threadfence();
        int nb = gridDim.x;
        float acc = 0.0f;
        for (int j = lane; j < nb; j += 32)
            acc += g_partials[j];
        #pragma unroll
        for (int o = 16; o > 0; o >>= 1)
            acc += __shfl_down_sync(0xffffffffu, acc, o);
        if (lane == 0) {
            out[0] = acc / (float)N;
            g_count = 0;   // reset for next graph replay
        }
    }
}

extern "C" void kernel_launch(void* const* d_in, const int* in_sizes, int n_in,
                              void* d_out, int out_size)
{
    const float* params = (const float*)d_in[0];
    const float* cp     = (const float*)d_in[1];
    const float* x0     = (const float*)d_in[2];
    const float* meas   = (const float*)d_in[3];
    float* out = (float*)d_out;

    int N = in_sizes[2] / 6;
    int T = in_sizes[3] / (N * 3);
    int nblocks = (N + SEGS_PER_BLOCK - 1) / SEGS_PER_BLOCK;
    size_t smem = (size_t)(T + 1) * sizeof(float4);

    ekf_kernel<<<nblocks, THREADS, smem>>>(params, cp, x0, meas, out, N, T);
}